// round 13
// baseline (speedup 1.0000x reference)
#include <cuda_runtime.h>
#include <cuda_bf16.h>
#include <cstdint>

// ---------------------------------------------------------------------------
// NCA step, persistent-CTA tensor-core version, TAP-DECOMPOSED stage 1:
// stage1 = 9 GEMMs (one per 3x3 tap), K=16 (12 ch + 4 zero pad), accumulated
// in registers. A panel = bf16-split patch stored ONCE (no im2col round-trip);
// tap shift folded into ldsm addressing. split-bf16: D = AhBh + AlBh + AhBl.
//   h   = conv(x) folded weights W1c (b1 added in regs before relu)
//   upd = relu(h) @ W2t + b2;  out = x + upd * (mask > 0.5)
// 148 persistent CTAs x 512 threads, all weights SMEM-resident, patch LDG
// prefetched into registers during previous tile's MMA.
// ---------------------------------------------------------------------------

#define Bn   16
#define Cn   12
#define Hn   384
#define Wn   384
#define CHn  96
#define PIX  128
#define NT   (3 * Hn * Bn)     // 18432 tiles
#define NCTA 148
#define NTHR 512

#define ASTR 48                // A row stride bytes (16 ch = 32B used + pad)
#define ADY  6240              // per-dy A block: 130 * 48
#define BSTR 32                // B row stride bytes (16 k-slots)

// SMEM layout (bytes)
#define SM_A     0             // A hi: 3*130*48 = 18720
#define SM_ALO   18720         // A lo: 18720
#define SM_B1    37440         // B1 hi: 9*96*32 = 27648
#define SM_B1LO  65088         // B1 lo: 27648
#define SM_B2    92736         // B2 hi: 96*32 = 3072
#define SM_B2LO  95808         // B2 lo: 3072
#define SM_UPD   98880         // partials: 2 x 128 x 16 f32 = 16384
#define SM_TOTAL 115264

__device__ unsigned char g_B1img[55296];   // [hi 27648][lo 27648]
__device__ unsigned char g_B2img[6144];    // [hi 3072][lo 3072]

static __device__ __forceinline__ uint32_t smem_u32(const void* p) {
    uint32_t a;
    asm("{ .reg .u64 t; cvta.to.shared.u64 t, %1; cvt.u32.u64 %0, t; }"
        : "=r"(a) : "l"(p));
    return a;
}
static __device__ __forceinline__ void ldsm4(uint32_t* r, uint32_t addr) {
    asm volatile("ldmatrix.sync.aligned.m8n8.x4.shared.b16 {%0,%1,%2,%3}, [%4];"
        : "=r"(r[0]), "=r"(r[1]), "=r"(r[2]), "=r"(r[3]) : "r"(addr));
}
static __device__ __forceinline__ void mma16816(float* d, const uint32_t* a,
                                                uint32_t b0, uint32_t b1) {
    asm volatile(
        "mma.sync.aligned.m16n8k16.row.col.f32.bf16.bf16.f32 "
        "{%0,%1,%2,%3}, {%4,%5,%6,%7}, {%8,%9}, {%0,%1,%2,%3};"
        : "+f"(d[0]), "+f"(d[1]), "+f"(d[2]), "+f"(d[3])
        : "r"(a[0]), "r"(a[1]), "r"(a[2]), "r"(a[3]), "r"(b0), "r"(b1));
}
static __device__ __forceinline__ uint32_t packbf(float v0, float v1) {
    uint32_t r;
    asm("cvt.rn.bf16x2.f32 %0, %1, %2;" : "=r"(r) : "f"(v1), "f"(v0));
    return r;
}
static __device__ __forceinline__ void split2relu(float v0, float v1,
                                                  uint32_t& hi, uint32_t& lo) {
    float a0 = fmaxf(v0, 0.f), a1 = fmaxf(v1, 0.f);
    __nv_bfloat16 h0 = __float2bfloat16(a0), h1 = __float2bfloat16(a1);
    float r0 = a0 - __bfloat162float(h0);
    float r1 = a1 - __bfloat162float(h1);
    __nv_bfloat162 hp; hp.x = h0; hp.y = h1;
    hi = *reinterpret_cast<uint32_t*>(&hp);
    lo = packbf(r0, r1);
}

// ---------------------------------------------------------------------------
// Fold kernel: W1c[k=c*9+dy*3+dx][o] = sum_p w1[o][p]*wperc[p][k].
// B1 image: row = (dy*3+dx)*96 + o, col slot = c (0..11, 12..15 zero pad).
// B2 image: row = (j>>4)*16 + oc, col slot = j&15.  32B row stride.
// ---------------------------------------------------------------------------
__global__ void fold_kernel(const float* __restrict__ w1,
                            const float* __restrict__ wperc,
                            const float* __restrict__ w2) {
    int tid = threadIdx.x;   // 512 threads, 1 block
    for (int i = tid; i < 55296 / 4; i += NTHR) ((uint32_t*)g_B1img)[i] = 0;
    for (int i = tid; i < 6144 / 4;  i += NTHR) ((uint32_t*)g_B2img)[i] = 0;
    __syncthreads();
    for (int idx = tid; idx < 108 * CHn; idx += NTHR) {
        int k = idx / CHn, o = idx % CHn;
        float v = 0.f;
        for (int p = 0; p < 48; ++p)
            v = fmaf(w1[o * 48 + p], wperc[p * 108 + k], v);
        int tt = k % 9, c = k / 9;
        __nv_bfloat16 h = __float2bfloat16(v);
        float r = v - __bfloat162float(h);
        __nv_bfloat16 l = __float2bfloat16(r);
        int off = (tt * 96 + o) * BSTR + c * 2;
        *(uint16_t*)(g_B1img + off)         = *(uint16_t*)&h;
        *(uint16_t*)(g_B1img + 27648 + off) = *(uint16_t*)&l;
    }
    for (int idx = tid; idx < 96 * Cn; idx += NTHR) {
        int j = idx / Cn, oc = idx % Cn;
        float v = w2[oc * CHn + j];
        __nv_bfloat16 h = __float2bfloat16(v);
        float r = v - __bfloat162float(h);
        __nv_bfloat16 l = __float2bfloat16(r);
        int off = ((j >> 4) * 16 + oc) * BSTR + (j & 15) * 2;
        *(uint16_t*)(g_B2img + off)        = *(uint16_t*)&h;
        *(uint16_t*)(g_B2img + 3072 + off) = *(uint16_t*)&l;
    }
}

// prefetch patch values for a tile into registers (wrap applied);
// idx = (c*3 + r)*130 + col  (coalesced over col within a warp)
static __device__ __forceinline__ void prefetch_patch(
    const float* __restrict__ x, int tile, int tid, float* pf) {
    int seg = tile % 3;
    int t1  = tile / 3;
    int gy  = t1 % Hn;
    int b   = t1 / Hn;
    int x0  = seg * PIX;
    int ym1 = (gy == 0) ? (Hn - 1) : gy - 1;
    int yp1 = (gy == Hn - 1) ? 0 : gy + 1;
#pragma unroll
    for (int j = 0; j < 10; ++j) {
        int idx = tid + j * NTHR;
        if (idx < Cn * 3 * 130) {
            int col = idx % 130;
            int t = idx / 130;
            int r = t % 3, c = t / 3;
            int gyy = (r == 0) ? ym1 : (r == 1 ? gy : yp1);
            int gx = x0 + col - 1;
            gx = (gx < 0) ? gx + Wn : (gx >= Wn ? gx - Wn : gx);
            pf[j] = __ldg(x + ((size_t)(b * Cn + c) * Hn + gyy) * Wn + gx);
        }
    }
}

// ---------------------------------------------------------------------------
__global__ __launch_bounds__(NTHR, 1)
void nca_mma(const float* __restrict__ x,
             const float* __restrict__ mask,
             const float* __restrict__ b1,
             const float* __restrict__ b2,
             float* __restrict__ out) {
    extern __shared__ char smc[];
    float* updp = (float*)(smc + SM_UPD);
    const uint32_t smb = smem_u32(smc);
    const int tid  = threadIdx.x;
    const int wid  = tid >> 5;
    const int lane = tid & 31;
    const int hf   = wid & 1;          // n-half (stage1) = k-half (stage2)
    const int ws   = (wid >> 1) * 16;  // m-stripe

    // ---- load all weights into SMEM once ----------------------------------
    for (int i = tid; i < 55296 / 16; i += NTHR)
        ((uint4*)(smc + SM_B1))[i] = ((const uint4*)g_B1img)[i];
    for (int i = tid; i < 6144 / 16; i += NTHR)
        ((uint4*)(smc + SM_B2))[i] = ((const uint4*)g_B2img)[i];
    // ---- zero A pad channels (c=12..15) once ------------------------------
    for (int i = tid; i < 780; i += NTHR) {
        int j = i >> 1, sel = i & 1;
        int dy = j / 130, p = j % 130;
        int off = dy * ADY + p * ASTR + 24 + sel * 4;
        *(uint32_t*)(smc + SM_A + off)   = 0;
        *(uint32_t*)(smc + SM_ALO + off) = 0;
    }

    // loop-invariant fragment addresses
    const uint32_t aRow = (lane & 7) + ((lane >> 3) & 1) * 8;   // 0..15
    const uint32_t aK2  = ((lane >> 4) & 1) * 16;
    const uint32_t addrA  = smb + SM_A   + (ws + aRow) * ASTR + aK2;
    const uint32_t addrAl = smb + SM_ALO + (ws + aRow) * ASTR + aK2;
    const uint32_t bN  = (lane & 7) + ((lane >> 4) & 1) * 8;
    const uint32_t bK2 = ((lane >> 3) & 1) * 16;
    const uint32_t addrB1 = smb + SM_B1 + (hf * 48 + bN) * BSTR + bK2;
    const uint32_t addrB2 = smb + SM_B2 + bN * BSTR + bK2;

    // b1 values for this thread's D registers: n = hf*48+np*16+hn*8+(lane&3)*2+cc
    float b1r[12];
#pragma unroll
    for (int i = 0; i < 6; ++i)
#pragma unroll
        for (int cc = 0; cc < 2; ++cc)
            b1r[i * 2 + cc] = __ldg(b1 + hf * 48 + (i >> 1) * 16 + (i & 1) * 8 +
                                    (lane & 3) * 2 + cc);

    float pf[10];
    int tile = blockIdx.x;
    prefetch_patch(x, tile, tid, pf);

    for (; tile < NT; tile += NCTA) {
        const int seg = tile % 3;
        const int t1  = tile / 3;
        const int gy  = t1 % Hn;
        const int b   = t1 / Hn;
        const int x0  = seg * PIX;

        // ---- commit prefetched patch DIRECTLY as bf16-split A panel -------
#pragma unroll
        for (int j = 0; j < 10; ++j) {
            int idx = tid + j * NTHR;
            if (idx < Cn * 3 * 130) {
                int col = idx % 130;
                int t = idx / 130;
                int r = t % 3, c = t / 3;
                float v = pf[j];
                __nv_bfloat16 h = __float2bfloat16(v);
                float rs = v - __bfloat162float(h);
                __nv_bfloat16 l = __float2bfloat16(rs);
                int off = r * ADY + col * ASTR + c * 2;
                *(uint16_t*)(smc + SM_A + off)   = *(uint16_t*)&h;
                *(uint16_t*)(smc + SM_ALO + off) = *(uint16_t*)&l;
            }
        }
        __syncthreads();                                   // sync1

        // ---- prefetch next tile's patch (lands during MMA) ----------------
        int ntile = tile + NCTA;
        if (ntile < NT) prefetch_patch(x, ntile, tid, pf);

        // ---- stage 1: 9 tap-GEMMs, 3 split chains, warp n-half ------------
        float d[6][4];
#pragma unroll
        for (int i = 0; i < 6; ++i)
#pragma unroll
            for (int j = 0; j < 4; ++j) d[i][j] = 0.f;

#pragma unroll
        for (int tt = 0; tt < 9; ++tt) {
            const int dy = tt / 3, dx = tt % 3;
            uint32_t ah[4], al[4], bh[3][4], bl[3][4];
            ldsm4(ah, addrA  + dy * ADY + dx * ASTR);
            ldsm4(al, addrAl + dy * ADY + dx * ASTR);
#pragma unroll
            for (int np = 0; np < 3; ++np) {
                uint32_t ab = addrB1 + (tt * 96 + np * 16) * BSTR;
                ldsm4(bh[np], ab);
                ldsm4(bl[np], ab + (SM_B1LO - SM_B1));
            }
#pragma unroll
            for (int np = 0; np < 3; ++np) {
                mma16816(d[2 * np],     ah, bh[np][0], bh[np][1]);
                mma16816(d[2 * np + 1], ah, bh[np][2], bh[np][3]);
            }
#pragma unroll
            for (int np = 0; np < 3; ++np) {
                mma16816(d[2 * np],     al, bh[np][0], bh[np][1]);
                mma16816(d[2 * np + 1], al, bh[np][2], bh[np][3]);
            }
#pragma unroll
            for (int np = 0; np < 3; ++np) {
                mma16816(d[2 * np],     ah, bl[np][0], bl[np][1]);
                mma16816(d[2 * np + 1], ah, bl[np][2], bl[np][3]);
            }
        }

        // ---- stage 2: A2 frags from D1 frags (+b1, relu, split) -----------
        float e[2][4];
#pragma unroll
        for (int i = 0; i < 2; ++i)
#pragma unroll
            for (int j = 0; j < 4; ++j) e[i][j] = 0.f;

#pragma unroll
        for (int j = 0; j < 3; ++j) {
            uint32_t a2h[4], a2l[4];
            split2relu(d[2 * j][0] + b1r[4 * j],
                       d[2 * j][1] + b1r[4 * j + 1], a2h[0], a2l[0]);
            split2relu(d[2 * j][2] + b1r[4 * j],
                       d[2 * j][3] + b1r[4 * j + 1], a2h[1], a2l[1]);
            split2relu(d[2 * j + 1][0] + b1r[4 * j + 2],
                       d[2 * j + 1][1] + b1r[4 * j + 3], a2h[2], a2l[2]);
            split2relu(d[2 * j + 1][2] + b1r[4 * j + 2],
                       d[2 * j + 1][3] + b1r[4 * j + 3], a2h[3], a2l[3]);
            int s2 = hf * 3 + j;
            uint32_t bh[4], bl[4];
            uint32_t ab = addrB2 + s2 * 16 * BSTR;
            ldsm4(bh, ab);
            ldsm4(bl, ab + (SM_B2LO - SM_B2));
            mma16816(e[0], a2h, bh[0], bh[1]);
            mma16816(e[1], a2h, bh[2], bh[3]);
            mma16816(e[0], a2l, bh[0], bh[1]);
            mma16816(e[1], a2l, bh[2], bh[3]);
            mma16816(e[0], a2h, bl[0], bl[1]);
            mma16816(e[1], a2h, bl[2], bl[3]);
        }

        // ---- store stage-2 partial sums (per k-half) ----------------------
        {
            int g = lane >> 2, t = lane & 3;
            float* up = updp + hf * 2048;
#pragma unroll
            for (int rr = 0; rr < 2; ++rr) {
                int px = ws + g + rr * 8;
#pragma unroll
                for (int cc = 0; cc < 2; ++cc)
                    up[px * 16 + 2 * t + cc] = e[0][rr * 2 + cc];
                if (t < 2) {
#pragma unroll
                    for (int cc = 0; cc < 2; ++cc)
                        up[px * 16 + 8 + 2 * t + cc] = e[1][rr * 2 + cc];
                }
            }
        }
        __syncthreads();                                   // sync2

        // ---- epilogue: out = x + (upd0+upd1+b2) * (mask>0.5) --------------
        {
            int px = tid & 127;
            float m = (mask[gy * Wn + x0 + px] > 0.5f) ? 1.f : 0.f;
#pragma unroll
            for (int k = 0; k < 3; ++k) {
                int oc = (tid >> 7) + 4 * k;
                float u = updp[px * 16 + oc] + updp[2048 + px * 16 + oc] +
                          __ldg(b2 + oc);
                size_t off = ((size_t)(b * Cn + oc) * Hn + gy) * Wn + x0 + px;
                out[off] = fmaf(u, m, __ldg(x + off));
            }
        }
        __syncthreads();                                   // sync3 (A/upd reuse)
    }
}

// ---------------------------------------------------------------------------
extern "C" void kernel_launch(void* const* d_in, const int* in_sizes, int n_in,
                              void* d_out, int out_size) {
    const float* x      = (const float*)d_in[0];
    const float* w_perc = (const float*)d_in[1];
    const float* w1     = (const float*)d_in[2];
    const float* b1     = (const float*)d_in[3];
    const float* w2     = (const float*)d_in[4];
    const float* b2     = (const float*)d_in[5];
    const float* mask   = (const float*)d_in[6];
    float* out          = (float*)d_out;

    cudaFuncSetAttribute(nca_mma, cudaFuncAttributeMaxDynamicSharedMemorySize,
                         SM_TOTAL);

    fold_kernel<<<1, NTHR>>>(w1, w_perc, w2);
    nca_mma<<<NCTA, NTHR, SM_TOTAL>>>(x, mask, b1, b2, out);
}

// round 14
// speedup vs baseline: 1.5188x; 1.5188x over previous
#include <cuda_runtime.h>
#include <cuda_fp16.h>
#include <cstdint>

// ---------------------------------------------------------------------------
// NCA step, persistent-CTA tensor-core version (mma.sync fp16, f32 accum).
// A (x patch) split-fp16: v = hi + lo; B (weights) single fp16:
//   D = Ah*B + Al*B   (2 chains; B-quant error ~2^-11 -> out rel ~2e-4).
//   stage1: h = im2col(x)[128px x 109] @ W1comb[109 x 96]  (bias as K-col)
//   stage2: upd = relu(h) @ W2t[96 x 12] + b2
//   out = x + upd * (mask > 0.5)
// 148 persistent CTAs x 512 threads; all weights SMEM-resident; patch LDG
// prefetched into registers during the previous tile's MMA phase.
// Warps: 8 m-stripes x 2 n-halves; stage-2 K-split partials summed via SMEM.
// ---------------------------------------------------------------------------

#define Bn   16
#define Cn   12
#define Hn   384
#define Wn   384
#define CHn  96
#define PIX  128
#define NT   (3 * Hn * Bn)     // 18432 tiles
#define NCTA 148
#define NTHR 512

#define ASTR 240               // A row stride bytes (112 k-slots + pad)
#define BSTR 48                // Bt row stride bytes (16 k-slots + pad)

// SMEM layout (bytes)
#define SM_A     0             // A hi: 128 x 240 = 30720
#define SM_ALO   30720         // A lo: 30720
#define SM_B1    61440         // B1t fp16: 672 x 48 = 32256
#define SM_B2    93696         // B2t fp16: 96 x 48 = 4608
#define SM_UPD   98304         // partials: 2 x 128 x 16 f32 = 16384
#define SM_PATCH 114688        // fp32 patch: 4680 floats = 18720
#define SM_TOTAL 133408

// Weight images (written by fold kernel)
__device__ unsigned char g_B1img[32256];
__device__ unsigned char g_B2img[4608];

static __device__ __forceinline__ uint32_t smem_u32(const void* p) {
    uint32_t a;
    asm("{ .reg .u64 t; cvta.to.shared.u64 t, %1; cvt.u32.u64 %0, t; }"
        : "=r"(a) : "l"(p));
    return a;
}
static __device__ __forceinline__ void ldsm4(uint32_t* r, uint32_t addr) {
    asm volatile("ldmatrix.sync.aligned.m8n8.x4.shared.b16 {%0,%1,%2,%3}, [%4];"
        : "=r"(r[0]), "=r"(r[1]), "=r"(r[2]), "=r"(r[3]) : "r"(addr));
}
static __device__ __forceinline__ void mma16816(float* d, const uint32_t* a,
                                                uint32_t b0, uint32_t b1) {
    asm volatile(
        "mma.sync.aligned.m16n8k16.row.col.f32.f16.f16.f32 "
        "{%0,%1,%2,%3}, {%4,%5,%6,%7}, {%8,%9}, {%0,%1,%2,%3};"
        : "+f"(d[0]), "+f"(d[1]), "+f"(d[2]), "+f"(d[3])
        : "r"(a[0]), "r"(a[1]), "r"(a[2]), "r"(a[3]), "r"(b0), "r"(b1));
}
static __device__ __forceinline__ uint32_t packh(float v0, float v1) {
    __half2 h = __floats2half2_rn(v0, v1);     // .x = v0 (low half)
    return *reinterpret_cast<uint32_t*>(&h);
}
// split v into fp16 hi + lo; pack pairs
static __device__ __forceinline__ void split2(float v0, float v1,
                                              uint32_t& hi, uint32_t& lo) {
    __half h0 = __float2half_rn(v0), h1 = __float2half_rn(v1);
    float r0 = v0 - __half2float(h0);
    float r1 = v1 - __half2float(h1);
    __half2 hp; hp.x = h0; hp.y = h1;
    hi = *reinterpret_cast<uint32_t*>(&hp);
    lo = packh(r0, r1);
}
static __device__ __forceinline__ void split2relu(float v0, float v1,
                                                  uint32_t& hi, uint32_t& lo) {
    split2(fmaxf(v0, 0.f), fmaxf(v1, 0.f), hi, lo);
}
static __device__ __forceinline__ float a_val(const float* pf, int px, int k) {
    if (k >= 108) return (k == 108) ? 1.f : 0.f;
    int c = k / 9, rem = k - c * 9;
    int dy = rem / 3, dx = rem - dy * 3;
    return pf[(c * 3 + dy) * 130 + px + dx];
}

// Fully-unrolled A build for one k-quarter (28 slots = 14 pairs); KBASE
// compile-time so the /9 and /3 index math constant-folds.
template <int KBASE>
static __device__ __forceinline__ void buildA(const float* pf, int px,
                                              char* Ah, char* Al) {
#pragma unroll
    for (int pr = 0; pr < 14; ++pr) {
        const int k0 = KBASE + 2 * pr;
        float v0 = a_val(pf, px, k0);
        float v1 = a_val(pf, px, k0 + 1);
        uint32_t hi, lo;
        split2(v0, v1, hi, lo);
        *(uint32_t*)(Ah + k0 * 2) = hi;
        *(uint32_t*)(Al + k0 * 2) = lo;
    }
}

// ---------------------------------------------------------------------------
// Fold: W1comb[k][o] = sum_p w1[o][p]*wperc[p][k]; Bt[n][k] row layout:
// B1 row = (k>>4)*96 + o (k=108 -> b1; 109..111 zero), B2 row =
// (j>>4)*16 + oc; 48B stride; single fp16.
// ---------------------------------------------------------------------------
__global__ void fold_kernel(const float* __restrict__ w1,
                            const float* __restrict__ wperc,
                            const float* __restrict__ b1,
                            const float* __restrict__ w2) {
    int tid = threadIdx.x;   // 512 threads, 1 block
    for (int i = tid; i < 32256 / 4; i += NTHR) ((uint32_t*)g_B1img)[i] = 0;
    for (int i = tid; i < 4608 / 4;  i += NTHR) ((uint32_t*)g_B2img)[i] = 0;
    __syncthreads();
    for (int idx = tid; idx < 109 * CHn; idx += NTHR) {
        int k = idx / CHn, o = idx % CHn;
        float v;
        if (k < 108) {
            v = 0.f;
            for (int p = 0; p < 48; ++p)
                v = fmaf(w1[o * 48 + p], wperc[p * 108 + k], v);
        } else v = b1[o];
        __half h = __float2half_rn(v);
        int off = ((k >> 4) * 96 + o) * BSTR + (k & 15) * 2;
        *(uint16_t*)(g_B1img + off) = *(uint16_t*)&h;
    }
    for (int idx = tid; idx < 96 * Cn; idx += NTHR) {
        int j = idx / Cn, oc = idx % Cn;
        __half h = __float2half_rn(w2[oc * CHn + j]);
        int off = ((j >> 4) * 16 + oc) * BSTR + (j & 15) * 2;
        *(uint16_t*)(g_B2img + off) = *(uint16_t*)&h;
    }
}

// prefetch patch for tile into registers (wrap padding applied)
static __device__ __forceinline__ void prefetch_patch(
    const float* __restrict__ x, int tile, int tid, float* pf) {
    int seg = tile % 3;
    int t1  = tile / 3;
    int gy  = t1 % Hn;
    int b   = t1 / Hn;
    int x0  = seg * PIX;
    int ym1 = (gy == 0) ? (Hn - 1) : gy - 1;
    int yp1 = (gy == Hn - 1) ? 0 : gy + 1;
#pragma unroll
    for (int j = 0; j < 10; ++j) {
        int idx = tid + j * NTHR;
        if (idx < Cn * 3 * 130) {
            int col = idx % 130;
            int t = idx / 130;
            int r = t % 3, c = t / 3;
            int gyy = (r == 0) ? ym1 : (r == 1 ? gy : yp1);
            int gx = x0 + col - 1;
            gx = (gx < 0) ? gx + Wn : (gx >= Wn ? gx - Wn : gx);
            pf[j] = __ldg(x + ((size_t)(b * Cn + c) * Hn + gyy) * Wn + gx);
        }
    }
}

// ---------------------------------------------------------------------------
__global__ __launch_bounds__(NTHR, 1)
void nca_mma(const float* __restrict__ x,
             const float* __restrict__ mask,
             const float* __restrict__ b2,
             float* __restrict__ out) {
    extern __shared__ char smc[];
    float* patchf = (float*)(smc + SM_PATCH);
    float* updp   = (float*)(smc + SM_UPD);
    const uint32_t smb = smem_u32(smc);
    const int tid  = threadIdx.x;
    const int wid  = tid >> 5;
    const int lane = tid & 31;
    const int hf   = wid & 1;          // n-half (stage1) = k-half (stage2)
    const int ws   = (wid >> 1) * 16;  // m-stripe

    // ---- load all weights into SMEM once ----------------------------------
    for (int i = tid; i < 32256 / 16; i += NTHR)
        ((uint4*)(smc + SM_B1))[i] = ((const uint4*)g_B1img)[i];
    for (int i = tid; i < 4608 / 16; i += NTHR)
        ((uint4*)(smc + SM_B2))[i] = ((const uint4*)g_B2img)[i];

    // loop-invariant fragment addresses
    const uint32_t aRow = ws + (lane & 7) + ((lane >> 3) & 1) * 8;
    const uint32_t aK2  = ((lane >> 4) & 1) * 16;
    const uint32_t addrA  = smb + SM_A   + aRow * ASTR + aK2;
    const uint32_t addrAl = smb + SM_ALO + aRow * ASTR + aK2;
    const uint32_t bN  = (lane & 7) + ((lane >> 4) & 1) * 8;
    const uint32_t bK2 = ((lane >> 3) & 1) * 16;
    const uint32_t addrB1 = smb + SM_B1 + (hf * 48 + bN) * BSTR + bK2;
    const uint32_t addrB2 = smb + SM_B2 + bN * BSTR + bK2;

    const int px128 = tid & 127;
    const int q     = tid >> 7;
    char* Ah = smc + SM_A   + px128 * ASTR;
    char* Al = smc + SM_ALO + px128 * ASTR;

    float pf[10];
    int tile = blockIdx.x;
    prefetch_patch(x, tile, tid, pf);

    for (; tile < NT; tile += NCTA) {
        const int seg = tile % 3;
        const int t1  = tile / 3;
        const int gy  = t1 % Hn;
        const int b   = t1 / Hn;
        const int x0  = seg * PIX;

        // ---- commit prefetched patch to SMEM ------------------------------
#pragma unroll
        for (int j = 0; j < 10; ++j) {
            int idx = tid + j * NTHR;
            if (idx < Cn * 3 * 130) patchf[idx] = pf[j];
        }
        __syncthreads();                                   // sync1

        // ---- build im2col A panels (one k-quarter per thread group) -------
        if      (q == 0) buildA<0>(patchf, px128, Ah, Al);
        else if (q == 1) buildA<28>(patchf, px128, Ah, Al);
        else if (q == 2) buildA<56>(patchf, px128, Ah, Al);
        else             buildA<84>(patchf, px128, Ah, Al);
        __syncthreads();                                   // sync2

        // ---- prefetch next tile's patch (lands during MMA) ----------------
        int ntile = tile + NCTA;
        if (ntile < NT) prefetch_patch(x, ntile, tid, pf);

        // ---- stage 1: 2 chains (Ah*B, Al*B), warp n-half ------------------
        float d[6][4];
#pragma unroll
        for (int i = 0; i < 6; ++i)
#pragma unroll
            for (int j = 0; j < 4; ++j) d[i][j] = 0.f;

#pragma unroll
        for (int s = 0; s < 7; ++s) {
            uint32_t ah[4], al[4], bh[3][4];
            ldsm4(ah, addrA  + s * 32);
            ldsm4(al, addrAl + s * 32);
#pragma unroll
            for (int np = 0; np < 3; ++np)
                ldsm4(bh[np], addrB1 + (s * 96 + np * 16) * BSTR);
#pragma unroll
            for (int np = 0; np < 3; ++np) {
                mma16816(d[2 * np],     ah, bh[np][0], bh[np][1]);
                mma16816(d[2 * np + 1], ah, bh[np][2], bh[np][3]);
            }
#pragma unroll
            for (int np = 0; np < 3; ++np) {
                mma16816(d[2 * np],     al, bh[np][0], bh[np][1]);
                mma16816(d[2 * np + 1], al, bh[np][2], bh[np][3]);
            }
        }

        // ---- stage 2: A2 frags from D1 frags (relu+split); B2 single ------
        float e[2][4];
#pragma unroll
        for (int i = 0; i < 2; ++i)
#pragma unroll
            for (int j = 0; j < 4; ++j) e[i][j] = 0.f;

#pragma unroll
        for (int j = 0; j < 3; ++j) {
            uint32_t a2h[4], a2l[4];
            split2relu(d[2 * j][0],     d[2 * j][1],     a2h[0], a2l[0]);
            split2relu(d[2 * j][2],     d[2 * j][3],     a2h[1], a2l[1]);
            split2relu(d[2 * j + 1][0], d[2 * j + 1][1], a2h[2], a2l[2]);
            split2relu(d[2 * j + 1][2], d[2 * j + 1][3], a2h[3], a2l[3]);
            int s2 = hf * 3 + j;
            uint32_t bh[4];
            ldsm4(bh, addrB2 + s2 * 16 * BSTR);
            mma16816(e[0], a2h, bh[0], bh[1]);
            mma16816(e[1], a2h, bh[2], bh[3]);
            mma16816(e[0], a2l, bh[0], bh[1]);
            mma16816(e[1], a2l, bh[2], bh[3]);
        }

        // ---- store stage-2 partial sums (per k-half) ----------------------
        {
            int g = lane >> 2, t = lane & 3;
            float* up = updp + hf * 2048;
#pragma unroll
            for (int rr = 0; rr < 2; ++rr) {
                int px = ws + g + rr * 8;
#pragma unroll
                for (int cc = 0; cc < 2; ++cc)
                    up[px * 16 + 2 * t + cc] = e[0][rr * 2 + cc];
                if (t < 2) {
#pragma unroll
                    for (int cc = 0; cc < 2; ++cc)
                        up[px * 16 + 8 + 2 * t + cc] = e[1][rr * 2 + cc];
                }
            }
        }
        __syncthreads();                                   // sync3

        // ---- epilogue: out = x + (upd0+upd1+b2) * (mask>0.5) --------------
        {
            int px = tid & 127;
            float m = (mask[gy * Wn + x0 + px] > 0.5f) ? 1.f : 0.f;
#pragma unroll
            for (int k = 0; k < 3; ++k) {
                int oc = (tid >> 7) + 4 * k;
                float u = updp[px * 16 + oc] + updp[2048 + px * 16 + oc] +
                          __ldg(b2 + oc);
                size_t off = ((size_t)(b * Cn + oc) * Hn + gy) * Wn + x0 + px;
                out[off] = fmaf(u, m, __ldg(x + off));
            }
        }
        __syncthreads();                                   // sync4 (A/upd reuse)
    }
}

// ---------------------------------------------------------------------------
extern "C" void kernel_launch(void* const* d_in, const int* in_sizes, int n_in,
                              void* d_out, int out_size) {
    const float* x      = (const float*)d_in[0];
    const float* w_perc = (const float*)d_in[1];
    const float* w1     = (const float*)d_in[2];
    const float* b1     = (const float*)d_in[3];
    const float* w2     = (const float*)d_in[4];
    const float* b2     = (const float*)d_in[5];
    const float* mask   = (const float*)d_in[6];
    float* out          = (float*)d_out;

    cudaFuncSetAttribute(nca_mma, cudaFuncAttributeMaxDynamicSharedMemorySize,
                         SM_TOTAL);

    fold_kernel<<<1, NTHR>>>(w1, w_perc, b1, w2);
    nca_mma<<<NCTA, NTHR, SM_TOTAL>>>(x, mask, b2, out);
}

// round 15
// speedup vs baseline: 1.8037x; 1.1876x over previous
#include <cuda_runtime.h>
#include <cuda_fp16.h>
#include <cstdint>

// ---------------------------------------------------------------------------
// NCA step, persistent-CTA tensor-core version (mma.sync fp16, f32 accum).
// A (x patch) split-fp16: v = hi + lo; B (weights) single fp16:
//   stage1: D = Ah*B + Al*B ; stage2: single-chain fp16 (err < B-quant floor)
//   h   = im2col(x) @ W1comb (bias as K-col); upd = relu(h) @ W2t + b2
//   out = x + upd * (mask > 0.5)
// This round: buildA stores vectorized to STS.128 (kills 4-way conflicts),
// upd partials stride 17 words (kills 16-way epilogue conflict), stage-2
// lo-chain dropped, redundant sync removed.
// ---------------------------------------------------------------------------

#define Bn   16
#define Cn   12
#define Hn   384
#define Wn   384
#define CHn  96
#define PIX  128
#define NT   (3 * Hn * Bn)     // 18432 tiles
#define NCTA 148
#define NTHR 512

#define ASTR 240               // A row stride bytes (112 k-slots + pad)
#define BSTR 48                // Bt row stride bytes (16 k-slots + pad)
#define USTR 17                // upd row stride (words); gcd(17,32)=1

// SMEM layout (bytes)
#define SM_A     0             // A hi: 128 x 240 = 30720
#define SM_ALO   30720         // A lo: 30720
#define SM_B1    61440         // B1t fp16: 672 x 48 = 32256
#define SM_B2    93696         // B2t fp16: 96 x 48 = 4608
#define SM_UPD   98304         // partials: 2 x 128 x 17 f32 = 17408
#define SM_PATCH 115712        // fp32 patch: 4680 floats = 18720
#define SM_TOTAL 134432

// Weight images (written by fold kernel)
__device__ unsigned char g_B1img[32256];
__device__ unsigned char g_B2img[4608];

static __device__ __forceinline__ uint32_t smem_u32(const void* p) {
    uint32_t a;
    asm("{ .reg .u64 t; cvta.to.shared.u64 t, %1; cvt.u32.u64 %0, t; }"
        : "=r"(a) : "l"(p));
    return a;
}
static __device__ __forceinline__ void ldsm4(uint32_t* r, uint32_t addr) {
    asm volatile("ldmatrix.sync.aligned.m8n8.x4.shared.b16 {%0,%1,%2,%3}, [%4];"
        : "=r"(r[0]), "=r"(r[1]), "=r"(r[2]), "=r"(r[3]) : "r"(addr));
}
static __device__ __forceinline__ void mma16816(float* d, const uint32_t* a,
                                                uint32_t b0, uint32_t b1) {
    asm volatile(
        "mma.sync.aligned.m16n8k16.row.col.f32.f16.f16.f32 "
        "{%0,%1,%2,%3}, {%4,%5,%6,%7}, {%8,%9}, {%0,%1,%2,%3};"
        : "+f"(d[0]), "+f"(d[1]), "+f"(d[2]), "+f"(d[3])
        : "r"(a[0]), "r"(a[1]), "r"(a[2]), "r"(a[3]), "r"(b0), "r"(b1));
}
static __device__ __forceinline__ uint32_t packh(float v0, float v1) {
    __half2 h = __floats2half2_rn(v0, v1);     // .x = v0 (low half)
    return *reinterpret_cast<uint32_t*>(&h);
}
static __device__ __forceinline__ uint32_t packrelu(float v0, float v1) {
    return packh(fmaxf(v0, 0.f), fmaxf(v1, 0.f));
}
// split v into fp16 hi + lo; pack pairs
static __device__ __forceinline__ void split2(float v0, float v1,
                                              uint32_t& hi, uint32_t& lo) {
    __half h0 = __float2half_rn(v0), h1 = __float2half_rn(v1);
    float r0 = v0 - __half2float(h0);
    float r1 = v1 - __half2float(h1);
    __half2 hp; hp.x = h0; hp.y = h1;
    hi = *reinterpret_cast<uint32_t*>(&hp);
    lo = packh(r0, r1);
}
static __device__ __forceinline__ float a_val(const float* pf, int px, int k) {
    if (k >= 108) return (k == 108) ? 1.f : 0.f;
    int c = k / 9, rem = k - c * 9;
    int dy = rem / 3, dx = rem - dy * 3;
    return pf[(c * 3 + dy) * 130 + px + dx];
}

// A build for one k-range [KBASE, KBASE+NSLOT), NSLOT multiple of 8 and
// KBASE*2 multiple of 16 -> all stores are aligned STS.128 (conflict-free
// at 240B lane stride: 8-lane phases hit 8 distinct banks).
template <int KBASE, int NSLOT>
static __device__ __forceinline__ void buildA(const float* pf, int px,
                                              char* Ah, char* Al) {
#pragma unroll
    for (int g = 0; g < NSLOT / 8; ++g) {
        const int k0 = KBASE + g * 8;
        uint4 hv, lv;
        split2(a_val(pf, px, k0 + 0), a_val(pf, px, k0 + 1), hv.x, lv.x);
        split2(a_val(pf, px, k0 + 2), a_val(pf, px, k0 + 3), hv.y, lv.y);
        split2(a_val(pf, px, k0 + 4), a_val(pf, px, k0 + 5), hv.z, lv.z);
        split2(a_val(pf, px, k0 + 6), a_val(pf, px, k0 + 7), hv.w, lv.w);
        *(uint4*)(Ah + k0 * 2) = hv;
        *(uint4*)(Al + k0 * 2) = lv;
    }
}

// ---------------------------------------------------------------------------
// Fold: W1comb[k][o] = sum_p w1[o][p]*wperc[p][k]; Bt[n][k] row layout:
// B1 row = (k>>4)*96 + o (k=108 -> b1; 109..111 zero), B2 row =
// (j>>4)*16 + oc; 48B stride; single fp16.
// ---------------------------------------------------------------------------
__global__ void fold_kernel(const float* __restrict__ w1,
                            const float* __restrict__ wperc,
                            const float* __restrict__ b1,
                            const float* __restrict__ w2) {
    int tid = threadIdx.x;   // 512 threads, 1 block
    for (int i = tid; i < 32256 / 4; i += NTHR) ((uint32_t*)g_B1img)[i] = 0;
    for (int i = tid; i < 4608 / 4;  i += NTHR) ((uint32_t*)g_B2img)[i] = 0;
    __syncthreads();
    for (int idx = tid; idx < 109 * CHn; idx += NTHR) {
        int k = idx / CHn, o = idx % CHn;
        float v;
        if (k < 108) {
            v = 0.f;
            for (int p = 0; p < 48; ++p)
                v = fmaf(w1[o * 48 + p], wperc[p * 108 + k], v);
        } else v = b1[o];
        __half h = __float2half_rn(v);
        int off = ((k >> 4) * 96 + o) * BSTR + (k & 15) * 2;
        *(uint16_t*)(g_B1img + off) = *(uint16_t*)&h;
    }
    for (int idx = tid; idx < 96 * Cn; idx += NTHR) {
        int j = idx / Cn, oc = idx % Cn;
        __half h = __float2half_rn(w2[oc * CHn + j]);
        int off = ((j >> 4) * 16 + oc) * BSTR + (j & 15) * 2;
        *(uint16_t*)(g_B2img + off) = *(uint16_t*)&h;
    }
}

// prefetch patch for tile into registers (wrap padding applied)
static __device__ __forceinline__ void prefetch_patch(
    const float* __restrict__ x, int tile, int tid, float* pf) {
    int seg = tile % 3;
    int t1  = tile / 3;
    int gy  = t1 % Hn;
    int b   = t1 / Hn;
    int x0  = seg * PIX;
    int ym1 = (gy == 0) ? (Hn - 1) : gy - 1;
    int yp1 = (gy == Hn - 1) ? 0 : gy + 1;
#pragma unroll
    for (int j = 0; j < 10; ++j) {
        int idx = tid + j * NTHR;
        if (idx < Cn * 3 * 130) {
            int col = idx % 130;
            int t = idx / 130;
            int r = t % 3, c = t / 3;
            int gyy = (r == 0) ? ym1 : (r == 1 ? gy : yp1);
            int gx = x0 + col - 1;
            gx = (gx < 0) ? gx + Wn : (gx >= Wn ? gx - Wn : gx);
            pf[j] = __ldg(x + ((size_t)(b * Cn + c) * Hn + gyy) * Wn + gx);
        }
    }
}

// ---------------------------------------------------------------------------
__global__ __launch_bounds__(NTHR, 1)
void nca_mma(const float* __restrict__ x,
             const float* __restrict__ mask,
             const float* __restrict__ b2,
             float* __restrict__ out) {
    extern __shared__ char smc[];
    float* patchf = (float*)(smc + SM_PATCH);
    float* updp   = (float*)(smc + SM_UPD);
    const uint32_t smb = smem_u32(smc);
    const int tid  = threadIdx.x;
    const int wid  = tid >> 5;
    const int lane = tid & 31;
    const int hf   = wid & 1;          // n-half (stage1) = k-half (stage2)
    const int ws   = (wid >> 1) * 16;  // m-stripe

    // ---- load all weights into SMEM once ----------------------------------
    for (int i = tid; i < 32256 / 16; i += NTHR)
        ((uint4*)(smc + SM_B1))[i] = ((const uint4*)g_B1img)[i];
    for (int i = tid; i < 4608 / 16; i += NTHR)
        ((uint4*)(smc + SM_B2))[i] = ((const uint4*)g_B2img)[i];

    // loop-invariant fragment addresses
    const uint32_t aRow = ws + (lane & 7) + ((lane >> 3) & 1) * 8;
    const uint32_t aK2  = ((lane >> 4) & 1) * 16;
    const uint32_t addrA  = smb + SM_A   + aRow * ASTR + aK2;
    const uint32_t addrAl = smb + SM_ALO + aRow * ASTR + aK2;
    const uint32_t bN  = (lane & 7) + ((lane >> 4) & 1) * 8;
    const uint32_t bK2 = ((lane >> 3) & 1) * 16;
    const uint32_t addrB1 = smb + SM_B1 + (hf * 48 + bN) * BSTR + bK2;
    const uint32_t addrB2 = smb + SM_B2 + bN * BSTR + bK2;

    const int px128 = tid & 127;
    const int q     = tid >> 7;
    char* Ah = smc + SM_A   + px128 * ASTR;
    char* Al = smc + SM_ALO + px128 * ASTR;

    float pf[10];
    int tile = blockIdx.x;
    prefetch_patch(x, tile, tid, pf);

    for (; tile < NT; tile += NCTA) {
        const int seg = tile % 3;
        const int t1  = tile / 3;
        const int gy  = t1 % Hn;
        const int b   = t1 / Hn;
        const int x0  = seg * PIX;

        // ---- commit prefetched patch to SMEM ------------------------------
#pragma unroll
        for (int j = 0; j < 10; ++j) {
            int idx = tid + j * NTHR;
            if (idx < Cn * 3 * 130) patchf[idx] = pf[j];
        }
        __syncthreads();                                   // sync1

        // ---- build im2col A panels (aligned k-ranges 32/24/32/24) ---------
        if      (q == 0) buildA<0,  32>(patchf, px128, Ah, Al);
        else if (q == 1) buildA<32, 24>(patchf, px128, Ah, Al);
        else if (q == 2) buildA<56, 32>(patchf, px128, Ah, Al);
        else             buildA<88, 24>(patchf, px128, Ah, Al);
        __syncthreads();                                   // sync2

        // ---- prefetch next tile's patch (lands during MMA) ----------------
        int ntile = tile + NCTA;
        if (ntile < NT) prefetch_patch(x, ntile, tid, pf);

        // ---- stage 1: 2 chains (Ah*B, Al*B), warp n-half ------------------
        float d[6][4];
#pragma unroll
        for (int i = 0; i < 6; ++i)
#pragma unroll
            for (int j = 0; j < 4; ++j) d[i][j] = 0.f;

#pragma unroll
        for (int s = 0; s < 7; ++s) {
            uint32_t ah[4], al[4], bh[3][4];
            ldsm4(ah, addrA  + s * 32);
            ldsm4(al, addrAl + s * 32);
#pragma unroll
            for (int np = 0; np < 3; ++np)
                ldsm4(bh[np], addrB1 + (s * 96 + np * 16) * BSTR);
#pragma unroll
            for (int np = 0; np < 3; ++np) {
                mma16816(d[2 * np],     ah, bh[np][0], bh[np][1]);
                mma16816(d[2 * np + 1], ah, bh[np][2], bh[np][3]);
            }
#pragma unroll
            for (int np = 0; np < 3; ++np) {
                mma16816(d[2 * np],     al, bh[np][0], bh[np][1]);
                mma16816(d[2 * np + 1], al, bh[np][2], bh[np][3]);
            }
        }

        // ---- stage 2: A2 frags from D1 frags (relu+pack, single chain) ----
        float e[2][4];
#pragma unroll
        for (int i = 0; i < 2; ++i)
#pragma unroll
            for (int j = 0; j < 4; ++j) e[i][j] = 0.f;

#pragma unroll
        for (int j = 0; j < 3; ++j) {
            uint32_t a2[4];
            a2[0] = packrelu(d[2 * j][0],     d[2 * j][1]);
            a2[1] = packrelu(d[2 * j][2],     d[2 * j][3]);
            a2[2] = packrelu(d[2 * j + 1][0], d[2 * j + 1][1]);
            a2[3] = packrelu(d[2 * j + 1][2], d[2 * j + 1][3]);
            int s2 = hf * 3 + j;
            uint32_t bh[4];
            ldsm4(bh, addrB2 + s2 * 16 * BSTR);
            mma16816(e[0], a2, bh[0], bh[1]);
            mma16816(e[1], a2, bh[2], bh[3]);
        }

        // ---- store stage-2 partial sums (per k-half; stride 17 words) -----
        {
            int g = lane >> 2, t = lane & 3;
            float* up = updp + hf * (PIX * USTR);
#pragma unroll
            for (int rr = 0; rr < 2; ++rr) {
                int px = ws + g + rr * 8;
#pragma unroll
                for (int cc = 0; cc < 2; ++cc)
                    up[px * USTR + 2 * t + cc] = e[0][rr * 2 + cc];
                if (t < 2) {
#pragma unroll
                    for (int cc = 0; cc < 2; ++cc)
                        up[px * USTR + 8 + 2 * t + cc] = e[1][rr * 2 + cc];
                }
            }
        }
        __syncthreads();                                   // sync3

        // ---- epilogue: out = x + (upd0+upd1+b2) * (mask>0.5) --------------
        {
            int px = tid & 127;
            float m = (mask[gy * Wn + x0 + px] > 0.5f) ? 1.f : 0.f;
#pragma unroll
            for (int k = 0; k < 3; ++k) {
                int oc = (tid >> 7) + 4 * k;
                float u = updp[px * USTR + oc] +
                          updp[PIX * USTR + px * USTR + oc] + __ldg(b2 + oc);
                size_t off = ((size_t)(b * Cn + oc) * Hn + gy) * Wn + x0 + px;
                out[off] = fmaf(u, m, __ldg(x + off));
            }
        }
        // next iteration's sync1 guards all cross-phase hazards (epilogue
        // reads updp; nothing before sync1 writes updp) -> no sync needed.
    }
}

// ---------------------------------------------------------------------------
extern "C" void kernel_launch(void* const* d_in, const int* in_sizes, int n_in,
                              void* d_out, int out_size) {
    const float* x      = (const float*)d_in[0];
    const float* w_perc = (const float*)d_in[1];
    const float* w1     = (const float*)d_in[2];
    const float* b1     = (const float*)d_in[3];
    const float* w2     = (const float*)d_in[4];
    const float* b2     = (const float*)d_in[5];
    const float* mask   = (const float*)d_in[6];
    float* out          = (float*)d_out;

    cudaFuncSetAttribute(nca_mma, cudaFuncAttributeMaxDynamicSharedMemorySize,
                         SM_TOTAL);

    fold_kernel<<<1, NTHR>>>(w1, w_perc, b1, w2);
    nca_mma<<<NCTA, NTHR, SM_TOTAL>>>(x, mask, b2, out);
}

// round 16
// speedup vs baseline: 2.2499x; 1.2474x over previous
#include <cuda_runtime.h>
#include <cuda_fp16.h>
#include <cstdint>

// ---------------------------------------------------------------------------
// NCA step, persistent-CTA tensor-core version (mma.sync fp16, f32 accum).
// BOTH operands single fp16 (A-split dropped; est. out rel err ~2e-4 < 1e-3):
//   stage1: h = im2col(x)[128px x 109] @ W1comb[109 x 96]  (bias as K-col)
//   stage2: upd = relu(h) @ W2t[96 x 12] + b2
//   out = x + upd * (mask > 0.5)
// 148 persistent CTAs x 512 threads; weights SMEM-resident; B2 fragments
// register-resident; prefetch index decomposition hoisted out of tile loop.
// Warps: 8 m-stripes x 2 n-halves; stage-2 K-split partials summed via SMEM.
// ---------------------------------------------------------------------------

#define Bn   16
#define Cn   12
#define Hn   384
#define Wn   384
#define CHn  96
#define PIX  128
#define NT   (3 * Hn * Bn)     // 18432 tiles
#define NCTA 148
#define NTHR 512

#define ASTR 240               // A row stride bytes (112 k-slots + pad)
#define BSTR 48                // Bt row stride bytes (16 k-slots + pad)
#define USTR 17                // upd row stride (words); gcd(17,32)=1

// SMEM layout (bytes)
#define SM_A     0             // A fp16: 128 x 240 = 30720
#define SM_B1    30720         // B1t fp16: 672 x 48 = 32256
#define SM_B2    62976         // B2t fp16: 96 x 48 = 4608
#define SM_UPD   67584         // partials: 2 x 128 x 17 f32 = 17408
#define SM_PATCH 84992         // fp32 patch: 4680 floats = 18720
#define SM_TOTAL 103712

// Weight images (written by fold kernel)
__device__ unsigned char g_B1img[32256];
__device__ unsigned char g_B2img[4608];

static __device__ __forceinline__ uint32_t smem_u32(const void* p) {
    uint32_t a;
    asm("{ .reg .u64 t; cvta.to.shared.u64 t, %1; cvt.u32.u64 %0, t; }"
        : "=r"(a) : "l"(p));
    return a;
}
static __device__ __forceinline__ void ldsm4(uint32_t* r, uint32_t addr) {
    asm volatile("ldmatrix.sync.aligned.m8n8.x4.shared.b16 {%0,%1,%2,%3}, [%4];"
        : "=r"(r[0]), "=r"(r[1]), "=r"(r[2]), "=r"(r[3]) : "r"(addr));
}
static __device__ __forceinline__ void mma16816(float* d, const uint32_t* a,
                                                uint32_t b0, uint32_t b1) {
    asm volatile(
        "mma.sync.aligned.m16n8k16.row.col.f32.f16.f16.f32 "
        "{%0,%1,%2,%3}, {%4,%5,%6,%7}, {%8,%9}, {%0,%1,%2,%3};"
        : "+f"(d[0]), "+f"(d[1]), "+f"(d[2]), "+f"(d[3])
        : "r"(a[0]), "r"(a[1]), "r"(a[2]), "r"(a[3]), "r"(b0), "r"(b1));
}
static __device__ __forceinline__ uint32_t packh(float v0, float v1) {
    __half2 h = __floats2half2_rn(v0, v1);     // .x = v0 (low half)
    return *reinterpret_cast<uint32_t*>(&h);
}
static __device__ __forceinline__ uint32_t packrelu(float v0, float v1) {
    return packh(fmaxf(v0, 0.f), fmaxf(v1, 0.f));
}
static __device__ __forceinline__ float a_val(const float* pf, int px, int k) {
    if (k >= 108) return (k == 108) ? 1.f : 0.f;
    int c = k / 9, rem = k - c * 9;
    int dy = rem / 3, dx = rem - dy * 3;
    return pf[(c * 3 + dy) * 130 + px + dx];
}

// A build (fp16, single panel) for k-range [KBASE, KBASE+NSLOT); KBASE*2
// multiple of 16 and NSLOT multiple of 8 -> aligned STS.128, conflict-free
// at 240B lane stride (8-lane phases hit 8 distinct banks).
template <int KBASE, int NSLOT>
static __device__ __forceinline__ void buildA(const float* pf, int px,
                                              char* Ah) {
#pragma unroll
    for (int g = 0; g < NSLOT / 8; ++g) {
        const int k0 = KBASE + g * 8;
        uint4 hv;
        hv.x = packh(a_val(pf, px, k0 + 0), a_val(pf, px, k0 + 1));
        hv.y = packh(a_val(pf, px, k0 + 2), a_val(pf, px, k0 + 3));
        hv.z = packh(a_val(pf, px, k0 + 4), a_val(pf, px, k0 + 5));
        hv.w = packh(a_val(pf, px, k0 + 6), a_val(pf, px, k0 + 7));
        *(uint4*)(Ah + k0 * 2) = hv;
    }
}

// ---------------------------------------------------------------------------
// Fold: W1comb[k][o] = sum_p w1[o][p]*wperc[p][k]; Bt[n][k] row layout:
// B1 row = (k>>4)*96 + o (k=108 -> b1; 109..111 zero), B2 row =
// (j>>4)*16 + oc; 48B stride; single fp16.
// ---------------------------------------------------------------------------
__global__ void fold_kernel(const float* __restrict__ w1,
                            const float* __restrict__ wperc,
                            const float* __restrict__ b1,
                            const float* __restrict__ w2) {
    int tid = threadIdx.x;   // 512 threads, 1 block
    for (int i = tid; i < 32256 / 4; i += NTHR) ((uint32_t*)g_B1img)[i] = 0;
    for (int i = tid; i < 4608 / 4;  i += NTHR) ((uint32_t*)g_B2img)[i] = 0;
    __syncthreads();
    for (int idx = tid; idx < 109 * CHn; idx += NTHR) {
        int k = idx / CHn, o = idx % CHn;
        float v;
        if (k < 108) {
            v = 0.f;
            for (int p = 0; p < 48; ++p)
                v = fmaf(w1[o * 48 + p], wperc[p * 108 + k], v);
        } else v = b1[o];
        __half h = __float2half_rn(v);
        int off = ((k >> 4) * 96 + o) * BSTR + (k & 15) * 2;
        *(uint16_t*)(g_B1img + off) = *(uint16_t*)&h;
    }
    for (int idx = tid; idx < 96 * Cn; idx += NTHR) {
        int j = idx / Cn, oc = idx % Cn;
        __half h = __float2half_rn(w2[oc * CHn + j]);
        int off = ((j >> 4) * 16 + oc) * BSTR + (j & 15) * 2;
        *(uint16_t*)(g_B2img + off) = *(uint16_t*)&h;
    }
}

// ---------------------------------------------------------------------------
__global__ __launch_bounds__(NTHR, 1)
void nca_mma(const float* __restrict__ x,
             const float* __restrict__ mask,
             const float* __restrict__ b2,
             float* __restrict__ out) {
    extern __shared__ char smc[];
    float* patchf = (float*)(smc + SM_PATCH);
    float* updp   = (float*)(smc + SM_UPD);
    const uint32_t smb = smem_u32(smc);
    const int tid  = threadIdx.x;
    const int wid  = tid >> 5;
    const int lane = tid & 31;
    const int hf   = wid & 1;          // n-half (stage1) = k-half (stage2)
    const int ws   = (wid >> 1) * 16;  // m-stripe

    // ---- load all weights into SMEM once ----------------------------------
    for (int i = tid; i < 32256 / 16; i += NTHR)
        ((uint4*)(smc + SM_B1))[i] = ((const uint4*)g_B1img)[i];
    for (int i = tid; i < 4608 / 16; i += NTHR)
        ((uint4*)(smc + SM_B2))[i] = ((const uint4*)g_B2img)[i];

    // loop-invariant fragment addresses
    const uint32_t aRow = ws + (lane & 7) + ((lane >> 3) & 1) * 8;
    const uint32_t aK2  = ((lane >> 4) & 1) * 16;
    const uint32_t addrA = smb + SM_A + aRow * ASTR + aK2;
    const uint32_t bN  = (lane & 7) + ((lane >> 4) & 1) * 8;
    const uint32_t bK2 = ((lane >> 3) & 1) * 16;
    const uint32_t addrB1 = smb + SM_B1 + (hf * 48 + bN) * BSTR + bK2;
    const uint32_t addrB2 = smb + SM_B2 + bN * BSTR + bK2;

    __syncthreads();   // weights visible before B2 fragment hoist

    // ---- B2 fragments register-resident (loop-invariant) ------------------
    uint32_t b2f[3][4];
#pragma unroll
    for (int j = 0; j < 3; ++j)
        ldsm4(b2f[j], addrB2 + (hf * 3 + j) * 16 * BSTR);

    // ---- per-thread prefetch constants (packed; hoisted out of loop) ------
    // meta = col | r<<8 | c<<10 ; -1 if inactive
    int meta[10];
#pragma unroll
    for (int j = 0; j < 10; ++j) {
        int idx = tid + j * NTHR;
        if (idx < Cn * 3 * 130) {
            int col = idx % 130;
            int t = idx / 130;
            meta[j] = col | ((t % 3) << 8) | ((t / 3) << 10);
        } else meta[j] = -1;
    }

    const int px128 = tid & 127;
    const int q     = tid >> 7;
    char* Ah = smc + SM_A + px128 * ASTR;

    // register prefetch of the first tile's patch
    float pf[10];
    int tile = blockIdx.x;
    {
        int seg = tile % 3, t1 = tile / 3;
        int gy = t1 % Hn, b = t1 / Hn, x0 = seg * PIX;
        int ym1 = (gy == 0) ? (Hn - 1) : gy - 1;
        int yp1 = (gy == Hn - 1) ? 0 : gy + 1;
#pragma unroll
        for (int j = 0; j < 10; ++j) {
            int m = meta[j];
            if (m >= 0) {
                int col = m & 255, r = (m >> 8) & 3, c = m >> 10;
                int gyy = (r == 0) ? ym1 : (r == 1 ? gy : yp1);
                int gx = x0 + col - 1;
                gx = (gx < 0) ? gx + Wn : (gx >= Wn ? gx - Wn : gx);
                pf[j] = __ldg(x + ((size_t)(b * Cn + c) * Hn + gyy) * Wn + gx);
            }
        }
    }

    for (; tile < NT; tile += NCTA) {
        const int seg = tile % 3;
        const int t1  = tile / 3;
        const int gy  = t1 % Hn;
        const int b   = t1 / Hn;
        const int x0  = seg * PIX;

        // ---- commit prefetched patch to SMEM ------------------------------
#pragma unroll
        for (int j = 0; j < 10; ++j) {
            int idx = tid + j * NTHR;
            if (idx < Cn * 3 * 130) patchf[idx] = pf[j];
        }
        __syncthreads();                                   // sync1

        // ---- build im2col A panel (fp16), aligned ranges 32/24/32/24 ------
        if      (q == 0) buildA<0,  32>(patchf, px128, Ah);
        else if (q == 1) buildA<32, 24>(patchf, px128, Ah);
        else if (q == 2) buildA<56, 32>(patchf, px128, Ah);
        else             buildA<88, 24>(patchf, px128, Ah);
        __syncthreads();                                   // sync2

        // ---- prefetch next tile's patch (lands during MMA) ----------------
        {
            int ntile = tile + NCTA;
            if (ntile < NT) {
                int nseg = ntile % 3, nt1 = ntile / 3;
                int ngy = nt1 % Hn, nb = nt1 / Hn, nx0 = nseg * PIX;
                int nym1 = (ngy == 0) ? (Hn - 1) : ngy - 1;
                int nyp1 = (ngy == Hn - 1) ? 0 : ngy + 1;
#pragma unroll
                for (int j = 0; j < 10; ++j) {
                    int m = meta[j];
                    if (m >= 0) {
                        int col = m & 255, r = (m >> 8) & 3, c = m >> 10;
                        int gyy = (r == 0) ? nym1 : (r == 1 ? ngy : nyp1);
                        int gx = nx0 + col - 1;
                        gx = (gx < 0) ? gx + Wn : (gx >= Wn ? gx - Wn : gx);
                        pf[j] = __ldg(x + ((size_t)(nb * Cn + c) * Hn + gyy) *
                                              Wn + gx);
                    }
                }
            }
        }

        // ---- stage 1: single chain A*B, warp n-half -----------------------
        float d[6][4];
#pragma unroll
        for (int i = 0; i < 6; ++i)
#pragma unroll
            for (int j = 0; j < 4; ++j) d[i][j] = 0.f;

#pragma unroll
        for (int s = 0; s < 7; ++s) {
            uint32_t ah[4], bh[3][4];
            ldsm4(ah, addrA + s * 32);
#pragma unroll
            for (int np = 0; np < 3; ++np)
                ldsm4(bh[np], addrB1 + (s * 96 + np * 16) * BSTR);
#pragma unroll
            for (int np = 0; np < 3; ++np) {
                mma16816(d[2 * np],     ah, bh[np][0], bh[np][1]);
                mma16816(d[2 * np + 1], ah, bh[np][2], bh[np][3]);
            }
        }

        // ---- stage 2: A2 frags from D1 frags; B2 register-resident --------
        float e[2][4];
#pragma unroll
        for (int i = 0; i < 2; ++i)
#pragma unroll
            for (int j = 0; j < 4; ++j) e[i][j] = 0.f;

#pragma unroll
        for (int j = 0; j < 3; ++j) {
            uint32_t a2[4];
            a2[0] = packrelu(d[2 * j][0],     d[2 * j][1]);
            a2[1] = packrelu(d[2 * j][2],     d[2 * j][3]);
            a2[2] = packrelu(d[2 * j + 1][0], d[2 * j + 1][1]);
            a2[3] = packrelu(d[2 * j + 1][2], d[2 * j + 1][3]);
            mma16816(e[0], a2, b2f[j][0], b2f[j][1]);
            mma16816(e[1], a2, b2f[j][2], b2f[j][3]);
        }

        // ---- store stage-2 partial sums (per k-half; stride 17 words) -----
        {
            int g = lane >> 2, t = lane & 3;
            float* up = updp + hf * (PIX * USTR);
#pragma unroll
            for (int rr = 0; rr < 2; ++rr) {
                int px = ws + g + rr * 8;
#pragma unroll
                for (int cc = 0; cc < 2; ++cc)
                    up[px * USTR + 2 * t + cc] = e[0][rr * 2 + cc];
                if (t < 2) {
#pragma unroll
                    for (int cc = 0; cc < 2; ++cc)
                        up[px * USTR + 8 + 2 * t + cc] = e[1][rr * 2 + cc];
                }
            }
        }
        __syncthreads();                                   // sync3

        // ---- epilogue: out = x + (upd0+upd1+b2) * (mask>0.5) --------------
        {
            int px = tid & 127;
            float m = (mask[gy * Wn + x0 + px] > 0.5f) ? 1.f : 0.f;
#pragma unroll
            for (int k = 0; k < 3; ++k) {
                int oc = (tid >> 7) + 4 * k;
                float u = updp[px * USTR + oc] +
                          updp[PIX * USTR + px * USTR + oc] + __ldg(b2 + oc);
                size_t off = ((size_t)(b * Cn + oc) * Hn + gy) * Wn + x0 + px;
                out[off] = fmaf(u, m, __ldg(x + off));
            }
        }
        // next iteration's sync1 guards all cross-phase hazards.
    }
}

// ---------------------------------------------------------------------------
extern "C" void kernel_launch(void* const* d_in, const int* in_sizes, int n_in,
                              void* d_out, int out_size) {
    const float* x      = (const float*)d_in[0];
    const float* w_perc = (const float*)d_in[1];
    const float* w1     = (const float*)d_in[2];
    const float* b1     = (const float*)d_in[3];
    const float* w2     = (const float*)d_in[4];
    const float* b2     = (const float*)d_in[5];
    const float* mask   = (const float*)d_in[6];
    float* out          = (float*)d_out;

    cudaFuncSetAttribute(nca_mma, cudaFuncAttributeMaxDynamicSharedMemorySize,
                         SM_TOTAL);

    fold_kernel<<<1, NTHR>>>(w1, w_perc, b1, w2);
    nca_mma<<<NCTA, NTHR, SM_TOTAL>>>(x, mask, b2, out);
}